// round 6
// baseline (speedup 1.0000x reference)
#include <cuda_runtime.h>
#include <cuda_bf16.h>
#include <cstdint>
#include <math.h>

constexpr int HDIM = 768;
constexpr int SEQ  = 256;
constexpr int NB   = 16;
constexpr int NK   = 32;
constexpr int KC   = 128;          // bytes (=elems) per chunk, 128B rows
constexpr int NCHUNK = HDIM / KC;  // 6
constexpr int BM   = 64;
constexpr int THREADS = 256;

// int8 hi/lo quantization of normalized embeddings + per-token scales
__device__ int8_t g_q8 [NB * SEQ * HDIM];
__device__ int8_t g_qr8[NB * SEQ * HDIM];
__device__ int8_t g_k8 [NK * SEQ * HDIM];
__device__ int8_t g_kr8[NK * SEQ * HDIM];
__device__ float  g_qa[NB * SEQ];
__device__ float  g_ka[NK * SEQ];

// smem: 2 buffers of (Qa 64 + Ra 64 + Kb 256 + Rb 256 = 640 rows x 128B), aux after
constexpr int ROWS_PER_BUF = 640;
constexpr int BUFSZ    = ROWS_PER_BUF * 128;   // 81920
constexpr int OFF_AUX  = 2 * BUFSZ;            // 163840
constexpr int OFF_WTAB = OFF_AUX;              // 256 f32
constexpr int OFF_KMF  = OFF_AUX + 1024;       // 256 f32 (k mask)
constexpr int OFF_KA   = OFF_AUX + 2048;       // 256 f32 (alpha_k)
constexpr int OFF_AQ   = OFF_AUX + 3072;       // 64 f32  (alpha_q rows)
constexpr int OFF_NUM  = OFF_AUX + 3328;       // 64*4 f32
constexpr int OFF_DEN  = OFF_AUX + 4352;       // 64*4 f32
constexpr int OFF_WSUM = OFF_AUX + 5376;       // 2 f32
constexpr int SMEM_TOTAL = OFF_AUX + 5440;     // 169280

__device__ __forceinline__ uint32_t smem_u32(const void* p) {
    uint32_t a;
    asm("{ .reg .u64 t; cvta.to.shared.u64 t, %1; cvt.u32.u64 %0, t; }" : "=r"(a) : "l"(p));
    return a;
}
#define CP_ASYNC(dst, src) \
    asm volatile("cp.async.cg.shared.global [%0], [%1], 16;" :: "r"(dst), "l"(src) : "memory")
#define CP_COMMIT() asm volatile("cp.async.commit_group;" ::: "memory")
#define CP_WAIT0()  asm volatile("cp.async.wait_group 0;" ::: "memory")

__device__ __forceinline__ void ldsm4(uint32_t* r, uint32_t addr) {
    asm volatile("ldmatrix.sync.aligned.m8n8.x4.shared.b16 {%0,%1,%2,%3}, [%4];"
                 : "=r"(r[0]), "=r"(r[1]), "=r"(r[2]), "=r"(r[3]) : "r"(addr));
}
__device__ __forceinline__ void imma(int* d, const uint32_t* a, uint32_t b0, uint32_t b1) {
    asm volatile("mma.sync.aligned.m16n8k32.row.col.s32.s8.s8.s32 "
                 "{%0,%1,%2,%3}, {%4,%5,%6,%7}, {%8,%9}, {%0,%1,%2,%3};"
                 : "+r"(d[0]), "+r"(d[1]), "+r"(d[2]), "+r"(d[3])
                 : "r"(a[0]), "r"(a[1]), "r"(a[2]), "r"(a[3]), "r"(b0), "r"(b1));
}

__global__ void zero_out_kernel(float* __restrict__ out) { out[threadIdx.x] = 0.0f; }

// normalize + int8 hi/lo quantize: x = alpha*(Q + R/128), alpha = max|x|/127
__global__ void normalize_kernel(const float* __restrict__ q, const float* __restrict__ k) {
    int tok = blockIdx.x;
    int tid = threadIdx.x;
    bool isq = tok < NB * SEQ;
    int t2 = isq ? tok : tok - NB * SEQ;
    const float* src = (isq ? q : k) + (size_t)t2 * HDIM;
    float v[3];
    float ss = 0.0f;
#pragma unroll
    for (int e = 0; e < 3; e++) { v[e] = src[tid + 256 * e]; ss += v[e] * v[e]; }
#pragma unroll
    for (int o = 16; o; o >>= 1) ss += __shfl_xor_sync(0xffffffffu, ss, o);
    __shared__ float red[8];
    __shared__ float totals, totalm;
    if ((tid & 31) == 0) red[tid >> 5] = ss;
    __syncthreads();
    if (tid < 8) {
        float s = red[tid];
#pragma unroll
        for (int o = 4; o; o >>= 1) s += __shfl_xor_sync(0xffu, s, o);
        if (tid == 0) totals = s;
    }
    __syncthreads();
    const float inv = 1.0f / fmaxf(sqrtf(totals), 1e-12f);
    float x[3];
    float ma = 0.0f;
#pragma unroll
    for (int e = 0; e < 3; e++) { x[e] = v[e] * inv; ma = fmaxf(ma, fabsf(x[e])); }
#pragma unroll
    for (int o = 16; o; o >>= 1) ma = fmaxf(ma, __shfl_xor_sync(0xffffffffu, ma, o));
    __syncthreads();
    if ((tid & 31) == 0) red[tid >> 5] = ma;
    __syncthreads();
    if (tid < 8) {
        float s = red[tid];
#pragma unroll
        for (int o = 4; o; o >>= 1) s = fmaxf(s, __shfl_xor_sync(0xffu, s, o));
        if (tid == 0) totalm = s;
    }
    __syncthreads();
    const float amax = totalm;
    const float alpha = amax / 127.0f;
    const float inva = 127.0f / amax;
#pragma unroll
    for (int e = 0; e < 3; e++) {
        int idx = tid + 256 * e;
        float t = x[e] * inva;
        int Q = __float2int_rn(t);
        int R = __float2int_rn((t - (float)Q) * 128.0f);
        if (isq) {
            g_q8 [(size_t)t2 * HDIM + idx] = (int8_t)Q;
            g_qr8[(size_t)t2 * HDIM + idx] = (int8_t)R;
        } else {
            g_k8 [(size_t)t2 * HDIM + idx] = (int8_t)Q;
            g_kr8[(size_t)t2 * HDIM + idx] = (int8_t)R;
        }
    }
    if (tid == 0) { if (isq) g_qa[t2] = alpha; else g_ka[t2] = alpha; }
}

__global__ __launch_bounds__(THREADS, 1)
void li_imma(const float* __restrict__ plsc, const float* __restrict__ paraw,
             const int* __restrict__ qmask, const int* __restrict__ kmask,
             float* __restrict__ out) {
    extern __shared__ __align__(128) char smem[];
    const uint32_t sb = smem_u32(smem);
    const int tid = threadIdx.x, lane = tid & 31, wid = tid >> 5;
    const int mb = blockIdx.x, jb = blockIdx.y, ib = blockIdx.z;

    float* wt   = (float*)(smem + OFF_WTAB);
    float* kf   = (float*)(smem + OFF_KMF);
    float* kav  = (float*)(smem + OFF_KA);
    float* aqs  = (float*)(smem + OFF_AQ);
    float* nums = (float*)(smem + OFF_NUM);
    float* dens = (float*)(smem + OFF_DEN);
    float* wsum = (float*)(smem + OFF_WSUM);

    const float scale = __expf(plsc[0]);
    const float ar = paraw[0];
    const float alpha = ar >= 0.0f ? ar : 0.01f * ar;
    if (tid < SEQ) {
        wt[tid]  = __expf(-alpha * (float)tid);
        kf[tid]  = (float)kmask[jb * SEQ + tid];
        kav[tid] = g_ka[jb * SEQ + tid];
    }
    if (tid < BM) aqs[tid] = g_qa[ib * SEQ + mb * BM + tid];

    // ---- loader: 640 rows/chunk; thread owns rows tid, tid+256, (+512 if tid<128)
    const int aq = ib * SEQ + mb * BM;
    const int bk = jb * SEQ;
    auto row_ptr = [&](int u) -> const int8_t* {
        if (u < 64)   return g_q8  + (size_t)(aq + u) * HDIM;
        if (u < 128)  return g_qr8 + (size_t)(aq + u - 64) * HDIM;
        if (u < 384)  return g_k8  + (size_t)(bk + u - 128) * HDIM;
        return g_kr8 + (size_t)(bk + u - 384) * HDIM;
    };
    const int u0 = tid, u1 = tid + 256, u2 = tid + 512;
    const int8_t* p0 = row_ptr(u0);
    const int8_t* p1 = row_ptr(u1);
    const int8_t* p2 = (tid < 128) ? row_ptr(u2) : nullptr;

    auto issue = [&](int it, int b) {
        const uint32_t base = sb + (uint32_t)b * BUFSZ;
        const int8_t* s;
        uint32_t d;
        s = p0 + it * KC; d = base + (uint32_t)u0 * 128u;
#pragma unroll
        for (uint32_t f = 0; f < 8; f++) CP_ASYNC(d + (((f ^ (u0 & 7)) & 7u) << 4), s + f * 16);
        s = p1 + it * KC; d = base + (uint32_t)u1 * 128u;
#pragma unroll
        for (uint32_t f = 0; f < 8; f++) CP_ASYNC(d + (((f ^ (u1 & 7)) & 7u) << 4), s + f * 16);
        if (tid < 128) {
            s = p2 + it * KC; d = base + (uint32_t)u2 * 128u;
#pragma unroll
            for (uint32_t f = 0; f < 8; f++) CP_ASYNC(d + (((f ^ (u2 & 7)) & 7u) << 4), s + f * 16);
        }
    };

    // ---- MMA: 2(m) x 4(n) warps, warp tile 32 x 64 ----
    const int mw = wid >> 2, nw = wid & 3;
    const int l15 = lane & 15, lhi = lane >> 4;
    int acc1[2][8][4], acc2[2][8][4];
#pragma unroll
    for (int im = 0; im < 2; im++)
#pragma unroll
        for (int tl = 0; tl < 8; tl++)
#pragma unroll
            for (int c = 0; c < 4; c++) { acc1[im][tl][c] = 0; acc2[im][tl][c] = 0; }

    auto compute = [&](int b) {
        const uint32_t base = sb + (uint32_t)b * BUFSZ;
        const uint32_t sQ = base, sR = base + 64u * 128u;
        const uint32_t sK = base + 128u * 128u, sRb = base + 384u * 128u;
#pragma unroll
        for (int ks = 0; ks < 4; ks++) {       // four k32 sub-chunks
            const uint32_t kc = (uint32_t)(2 * ks + lhi);
            uint32_t aQ[2][4], aR[2][4];
#pragma unroll
            for (int im = 0; im < 2; im++) {
                const uint32_t ro = (uint32_t)(mw * 32 + im * 16 + l15);
                const uint32_t off = ro * 128u + ((kc ^ (ro & 7u)) << 4);
                ldsm4(aQ[im], sQ + off);
                ldsm4(aR[im], sR + off);
            }
#pragma unroll
            for (int ng = 0; ng < 4; ng++) {   // n-groups of 16
                const uint32_t ro = (uint32_t)(nw * 64 + ng * 16 + l15);
                const uint32_t off = ro * 128u + ((kc ^ (ro & 7u)) << 4);
                uint32_t bK[4], bR[4];
                ldsm4(bK, sK + off);
                ldsm4(bR, sRb + off);
#pragma unroll
                for (int im = 0; im < 2; im++)
#pragma unroll
                    for (int h = 0; h < 2; h++) {
                        const int tl = ng * 2 + h;
                        imma(acc1[im][tl], aQ[im], bK[h], bK[h + 2]);
                        imma(acc2[im][tl], aQ[im], bR[h], bR[h + 2]);
                        imma(acc2[im][tl], aR[im], bK[h], bK[h + 2]);
                    }
            }
        }
    };

    // ---- double-buffered pipeline, one barrier per chunk ----
    issue(0, 0); CP_COMMIT();
#pragma unroll 1
    for (int it = 0; it < NCHUNK; ++it) {
        CP_WAIT0();
        __syncthreads();   // chunk `it` visible; buf (it+1)&1 drained by all warps
        if (it + 1 < NCHUNK) { issue(it + 1, (it + 1) & 1); CP_COMMIT(); }
        compute(it & 1);
    }

    // ---- epilogue: C = aq*ak*(S1 + S2/128); softmax + sum p*C ----
    float pn[4] = {0, 0, 0, 0}, pd[4] = {0, 0, 0, 0};
    const int colq = 2 * (lane & 3);
    const int rowq = lane >> 2;
#pragma unroll
    for (int im = 0; im < 2; im++)
#pragma unroll
        for (int hi = 0; hi < 2; hi++) {
            const int r = mw * 32 + im * 16 + hi * 8 + rowq;
            const int s = mb * BM + r;
            const float aqa = aqs[r];
            const int slot = im * 2 + hi;
#pragma unroll
            for (int tl = 0; tl < 8; tl++)
#pragma unroll
                for (int e = 0; e < 2; e++) {
                    const int t = nw * 64 + tl * 8 + colq + e;
                    const float C = aqa * kav[t] *
                        ((float)acc1[im][tl][hi * 2 + e] +
                         (float)acc2[im][tl][hi * 2 + e] * 0.0078125f);
                    int d = s - t; d = d < 0 ? -d : d;
                    const float ex = kf[t] * __expf(scale * wt[d] * C);
                    pd[slot] += ex;
                    pn[slot] += ex * C;
                }
        }
#pragma unroll
    for (int o = 1; o <= 2; o <<= 1)
#pragma unroll
        for (int k = 0; k < 4; k++) {
            pn[k] += __shfl_xor_sync(0xffffffffu, pn[k], o);
            pd[k] += __shfl_xor_sync(0xffffffffu, pd[k], o);
        }
    if ((lane & 3) == 0)
#pragma unroll
        for (int k = 0; k < 4; k++) {
            const int r = mw * 32 + (k >> 1) * 16 + (k & 1) * 8 + rowq;
            nums[r * 4 + nw] = pn[k];
            dens[r * 4 + nw] = pd[k];
        }
    __syncthreads();
    if (tid < 64) {
        float n = 0.0f, d = 0.0f;
#pragma unroll
        for (int w = 0; w < 4; w++) { n += nums[tid * 4 + w]; d += dens[tid * 4 + w]; }
        float pt = d > 0.0f ? n / d : 0.0f;
        pt *= (float)qmask[ib * SEQ + mb * BM + tid];
#pragma unroll
        for (int o = 16; o; o >>= 1) pt += __shfl_xor_sync(0xffffffffu, pt, o);
        if (lane == 0) wsum[tid >> 5] = pt;
    }
    __syncthreads();
    if (tid == 0) atomicAdd(&out[ib * NK + jb], wsum[0] + wsum[1]);
}

extern "C" void kernel_launch(void* const* d_in, const int* in_sizes, int n_in,
                              void* d_out, int out_size) {
    const float* q    = (const float*)d_in[0];
    const float* k    = (const float*)d_in[1];
    const float* lsc  = (const float*)d_in[2];
    const float* araw = (const float*)d_in[3];
    const int*   qm   = (const int*)d_in[4];
    const int*   km   = (const int*)d_in[5];
    float* out = (float*)d_out;

    cudaFuncSetAttribute(li_imma, cudaFuncAttributeMaxDynamicSharedMemorySize, SMEM_TOTAL);
    zero_out_kernel<<<1, NB * NK>>>(out);
    normalize_kernel<<<NB * SEQ + NK * SEQ, 256>>>(q, k);
    li_imma<<<dim3(SEQ / BM, NK, NB), THREADS, SMEM_TOTAL>>>(lsc, araw, qm, km, out);
}

// round 7
// speedup vs baseline: 3.1202x; 3.1202x over previous
#include <cuda_runtime.h>
#include <cuda_bf16.h>
#include <cstdint>
#include <math.h>

constexpr int HDIM = 768;
constexpr int SEQ  = 256;
constexpr int NB   = 16;
constexpr int NK   = 32;
constexpr int KC   = 32;           // K elems per chunk (64B half-row)
constexpr int NCHUNK = HDIM / KC;  // 24
constexpr int BM   = 64;
constexpr int THREADS = 256;

__device__ __nv_bfloat16 g_qh[NB * SEQ * HDIM];
__device__ __nv_bfloat16 g_ql[NB * SEQ * HDIM];
__device__ __nv_bfloat16 g_kh[NK * SEQ * HDIM];
__device__ __nv_bfloat16 g_kl[NK * SEQ * HDIM];

// smem: 640 rows x 128B; each 128B row holds BOTH buffers (64B halves, bit6 of
// the swizzled column selects the buffer). Tiles: Ah rows 0-63, Al 64-127,
// Bh 128-383, Bl 384-639.
constexpr int TILES_SZ  = 640 * 128;          // 81920
constexpr int OFF_WTAB  = TILES_SZ;           // 256 f32
constexpr int OFF_KMF   = OFF_WTAB + 1024;    // 256 f32
constexpr int OFF_NUM   = OFF_KMF + 1024;     // 64*4 f32
constexpr int OFF_DEN   = OFF_NUM + 1024;     // 64*4 f32
constexpr int OFF_WSUM  = OFF_DEN + 1024;     // 2 f32
constexpr int SMEM_TOTAL = OFF_WSUM + 64;     // 86144

__device__ __forceinline__ uint32_t smem_u32(const void* p) {
    uint32_t a;
    asm("{ .reg .u64 t; cvta.to.shared.u64 t, %1; cvt.u32.u64 %0, t; }" : "=r"(a) : "l"(p));
    return a;
}
#define CP_ASYNC(dst, src) \
    asm volatile("cp.async.cg.shared.global [%0], [%1], 16;" :: "r"(dst), "l"(src) : "memory")
#define CP_COMMIT() asm volatile("cp.async.commit_group;" ::: "memory")
#define CP_WAIT0()  asm volatile("cp.async.wait_group 0;" ::: "memory")

__device__ __forceinline__ void ldsm4(uint32_t* r, uint32_t addr) {
    asm volatile("ldmatrix.sync.aligned.m8n8.x4.shared.b16 {%0,%1,%2,%3}, [%4];"
                 : "=r"(r[0]), "=r"(r[1]), "=r"(r[2]), "=r"(r[3]) : "r"(addr));
}
__device__ __forceinline__ void mma16816(float* d, const uint32_t* a, uint32_t b0, uint32_t b1) {
    asm volatile("mma.sync.aligned.m16n8k16.row.col.f32.bf16.bf16.f32 "
                 "{%0,%1,%2,%3}, {%4,%5,%6,%7}, {%8,%9}, {%0,%1,%2,%3};"
                 : "+f"(d[0]), "+f"(d[1]), "+f"(d[2]), "+f"(d[3])
                 : "r"(a[0]), "r"(a[1]), "r"(a[2]), "r"(a[3]), "r"(b0), "r"(b1));
}

__global__ void zero_out_kernel(float* __restrict__ out) { out[threadIdx.x] = 0.0f; }

__global__ void normalize_kernel(const float* __restrict__ q, const float* __restrict__ k) {
    int tok = blockIdx.x;
    int tid = threadIdx.x;
    bool isq = tok < NB * SEQ;
    int t2 = isq ? tok : tok - NB * SEQ;
    const float* src = (isq ? q : k) + (size_t)t2 * HDIM;
    float v[3];
    float ss = 0.0f;
#pragma unroll
    for (int e = 0; e < 3; e++) { v[e] = src[tid + 256 * e]; ss += v[e] * v[e]; }
#pragma unroll
    for (int o = 16; o; o >>= 1) ss += __shfl_xor_sync(0xffffffffu, ss, o);
    __shared__ float red[8];
    __shared__ float total;
    if ((tid & 31) == 0) red[tid >> 5] = ss;
    __syncthreads();
    if (tid < 8) {
        float s = red[tid];
#pragma unroll
        for (int o = 4; o; o >>= 1) s += __shfl_xor_sync(0xffu, s, o);
        if (tid == 0) total = s;
    }
    __syncthreads();
    float inv = 1.0f / fmaxf(sqrtf(total), 1e-12f);
#pragma unroll
    for (int e = 0; e < 3; e++) {
        int idx = tid + 256 * e;
        float x = v[e] * inv;
        __nv_bfloat16 h = __float2bfloat16(x);
        __nv_bfloat16 l = __float2bfloat16(x - __bfloat162float(h));
        if (isq) {
            g_qh[(size_t)t2 * HDIM + idx] = h;
            g_ql[(size_t)t2 * HDIM + idx] = l;
        } else {
            g_kh[(size_t)t2 * HDIM + idx] = h;
            g_kl[(size_t)t2 * HDIM + idx] = l;
        }
    }
}

__global__ __launch_bounds__(THREADS, 2)
void li_hmma(const float* __restrict__ plsc, const float* __restrict__ paraw,
             const int* __restrict__ qmask, const int* __restrict__ kmask,
             float* __restrict__ out) {
    extern __shared__ __align__(128) char smem[];
    const uint32_t sb = smem_u32(smem);
    const int tid = threadIdx.x, lane = tid & 31, wid = tid >> 5;
    const int mb = blockIdx.x, jb = blockIdx.y, ib = blockIdx.z;

    float* wt   = (float*)(smem + OFF_WTAB);
    float* kf   = (float*)(smem + OFF_KMF);
    float* nums = (float*)(smem + OFF_NUM);
    float* dens = (float*)(smem + OFF_DEN);
    float* wsum = (float*)(smem + OFF_WSUM);

    const float scale = __expf(plsc[0]);
    const float ar = paraw[0];
    const float alpha = ar >= 0.0f ? ar : 0.01f * ar;
    if (tid < SEQ) {
        wt[tid] = __expf(-alpha * (float)tid);
        kf[tid] = (float)kmask[jb * SEQ + tid];
    }

    // ---- loader: r0 = tid>>2 in [0,64), f = tid&3; thread covers row r0+64i
    //      for i in 0..9 (i=0 Ah, 1 Al, 2-5 Bh, 6-9 Bl), one 16B piece per row.
    const int r0 = tid >> 2, f = tid & 3;
    const size_t offA = (size_t)(ib * SEQ + mb * BM + r0) * HDIM + f * 8;
    const size_t offB = (size_t)(jb * SEQ + r0) * HDIM + f * 8;
    const __nv_bfloat16* sAh = g_qh + offA;
    const __nv_bfloat16* sAl = g_ql + offA;
    const __nv_bfloat16* sBh = g_kh + offB;
    const __nv_bfloat16* sBl = g_kl + offB;
    // dst base: row r0, swizzled column (f ^ (r0&7)); row r0+64i => +i*8192,
    // buffer b flips bit 6 of the column term.
    const uint32_t dstb = sb + (uint32_t)r0 * 128u + (uint32_t)(((f ^ (r0 & 7)) & 7) << 4);

    auto issue = [&](int it, uint32_t bx) {
        const int ko = it * KC;
        CP_ASYNC((dstb + 0 * 8192) ^ bx, sAh + ko);
        CP_ASYNC((dstb + 1 * 8192) ^ bx, sAl + ko);
#pragma unroll
        for (int j = 0; j < 4; j++)
            CP_ASYNC((dstb + (2 + j) * 8192) ^ bx, sBh + j * (64 * HDIM) + ko);
#pragma unroll
        for (int j = 0; j < 4; j++)
            CP_ASYNC((dstb + (6 + j) * 8192) ^ bx, sBl + j * (64 * HDIM) + ko);
    };

    // ---- MMA: 2(m) x 4(n) warps; warp tile 32 x 64; 3-pass bf16 split ----
    const int mw = wid >> 2, nw = wid & 3;
    const int l15 = lane & 15, lhi = lane >> 4;
    float acc[2][8][4];
#pragma unroll
    for (int im = 0; im < 2; im++)
#pragma unroll
        for (int tl = 0; tl < 8; tl++)
#pragma unroll
            for (int c = 0; c < 4; c++) acc[im][tl][c] = 0.0f;

    auto compute = [&](uint32_t bx) {
#pragma unroll
        for (int ks = 0; ks < 2; ks++) {     // two k16 slices per KC=32 chunk
            const uint32_t kc = (uint32_t)(2 * ks + lhi);   // 16B col in half-row
            uint32_t ah[2][4], al[2][4];
#pragma unroll
            for (int im = 0; im < 2; im++) {
                const uint32_t ro = (uint32_t)(mw * 32 + im * 16 + l15);
                const uint32_t co = ((kc ^ (ro & 7u)) << 4) ^ bx;
                ldsm4(ah[im], sb + ro * 128u + co);                  // Ah
                ldsm4(al[im], sb + 8192u + ro * 128u + co);          // Al
            }
#pragma unroll
            for (int ng = 0; ng < 4; ng++) {
                const uint32_t ro = (uint32_t)(nw * 64 + ng * 16 + l15);
                const uint32_t co = ((kc ^ (ro & 7u)) << 4) ^ bx;
                uint32_t bh[4], bl[4];
                ldsm4(bh, sb + 16384u + ro * 128u + co);             // Bh
                ldsm4(bl, sb + 49152u + ro * 128u + co);             // Bl
#pragma unroll
                for (int im = 0; im < 2; im++)
#pragma unroll
                    for (int o = 0; o < 2; o++) {
                        const int tl = ng * 2 + o;
                        mma16816(acc[im][tl], ah[im], bh[o], bh[o + 2]);
                        mma16816(acc[im][tl], al[im], bh[o], bh[o + 2]);
                        mma16816(acc[im][tl], ah[im], bl[o], bl[o + 2]);
                    }
            }
        }
    };

    // ---- pipeline: half-row double buffer, ONE barrier per chunk ----
    issue(0, 0); CP_COMMIT();
#pragma unroll 1
    for (int it = 0; it < NCHUNK; ++it) {
        CP_WAIT0();
        __syncthreads();   // chunk `it` visible; other half drained by compute(it-1)
        if (it + 1 < NCHUNK) { issue(it + 1, (uint32_t)(((it + 1) & 1) << 6)); CP_COMMIT(); }
        compute((uint32_t)((it & 1) << 6));
    }

    // ---- epilogue: softmax (no max-sub; |logit| <= scale) + sum p*C ----
    float pn[4] = {0, 0, 0, 0}, pd[4] = {0, 0, 0, 0};
    const int colq = 2 * (lane & 3);
    const int rowq = lane >> 2;
#pragma unroll
    for (int im = 0; im < 2; im++)
#pragma unroll
        for (int hi = 0; hi < 2; hi++) {
            const int r = mw * 32 + im * 16 + hi * 8 + rowq;
            const int s = mb * BM + r;
            const int slot = im * 2 + hi;
#pragma unroll
            for (int tl = 0; tl < 8; tl++)
#pragma unroll
                for (int e = 0; e < 2; e++) {
                    const float C = acc[im][tl][hi * 2 + e];
                    const int t = nw * 64 + tl * 8 + colq + e;
                    int d = s - t; d = d < 0 ? -d : d;
                    const float ex = kf[t] * __expf(scale * wt[d] * C);
                    pd[slot] += ex;
                    pn[slot] += ex * C;
                }
        }
#pragma unroll
    for (int o = 1; o <= 2; o <<= 1)
#pragma unroll
        for (int k = 0; k < 4; k++) {
            pn[k] += __shfl_xor_sync(0xffffffffu, pn[k], o);
            pd[k] += __shfl_xor_sync(0xffffffffu, pd[k], o);
        }
    if ((lane & 3) == 0)
#pragma unroll
        for (int k = 0; k < 4; k++) {
            const int r = mw * 32 + (k >> 1) * 16 + (k & 1) * 8 + rowq;
            nums[r * 4 + nw] = pn[k];
            dens[r * 4 + nw] = pd[k];
        }
    __syncthreads();
    if (tid < 64) {
        float n = 0.0f, d = 0.0f;
#pragma unroll
        for (int w = 0; w < 4; w++) { n += nums[tid * 4 + w]; d += dens[tid * 4 + w]; }
        float pt = d > 0.0f ? n / d : 0.0f;
        pt *= (float)qmask[ib * SEQ + mb * BM + tid];
#pragma unroll
        for (int o = 16; o; o >>= 1) pt += __shfl_xor_sync(0xffffffffu, pt, o);
        if (lane == 0) wsum[tid >> 5] = pt;
    }
    __syncthreads();
    if (tid == 0) atomicAdd(&out[ib * NK + jb], wsum[0] + wsum[1]);
}

extern "C" void kernel_launch(void* const* d_in, const int* in_sizes, int n_in,
                              void* d_out, int out_size) {
    const float* q    = (const float*)d_in[0];
    const float* k    = (const float*)d_in[1];
    const float* lsc  = (const float*)d_in[2];
    const float* araw = (const float*)d_in[3];
    const int*   qm   = (const int*)d_in[4];
    const int*   km   = (const int*)d_in[5];
    float* out = (float*)d_out;

    cudaFuncSetAttribute(li_hmma, cudaFuncAttributeMaxDynamicSharedMemorySize, SMEM_TOTAL);
    zero_out_kernel<<<1, NB * NK>>>(out);
    normalize_kernel<<<NB * SEQ + NK * SEQ, 256>>>(q, k);
    li_hmma<<<dim3(SEQ / BM, NK, NB), THREADS, SMEM_TOTAL>>>(lsc, araw, qm, km, out);
}